// round 15
// baseline (speedup 1.0000x reference)
#include <cuda_runtime.h>
#include <cuda_fp16.h>

// Problem constants (fixed by the reference: B=4, N=1024, FMAP=64, HID=32)
#define BB 4
#define NN 1024
#define FM 64
#define HID 32
#define ROWS (BB * NN)        // 4096
#define I_CHUNK 32
#define JT 128
#define NBLOCKS 1024          // (8, 32, 4) — single wave, all co-resident

// Projections, packed as half (32 per row = 16 half2). Written in phase A.
__device__ __align__(16) __half2 g_A[ROWS * 16];  // A' = X@W1a + b1
__device__ __align__(16) __half2 g_C[ROWS * 16];  // C  = X@W1b

// Grid barrier state (replay-safe: count self-resets, gen is monotone).
__device__ unsigned g_count;   // zero-init at module load
__device__ unsigned g_gen;

__device__ __forceinline__ __half2 tanh2_approx(__half2 x) {
    unsigned xi = *reinterpret_cast<unsigned*>(&x);
    unsigned ri;
    asm("tanh.approx.f16x2 %0, %1;" : "=r"(ri) : "r"(xi));
    return *reinterpret_cast<__half2*>(&ri);
}

__device__ __forceinline__ float tanhf_approx(float x) {
    float r;
    asm("tanh.approx.f32 %0, %1;" : "=f"(r) : "f"(x));
    return r;
}

__global__ __launch_bounds__(JT, 8) void fused_kernel(
    const float* __restrict__ X,    // [ROWS, 64]
    const float* __restrict__ W1,   // [128, 32]
    const float* __restrict__ b1,   // [32]
    const float* __restrict__ W2,   // [32]
    const float* __restrict__ b2,   // [1]
    float* __restrict__ out)        // [B, N, N]
{
    // Phase A: sW = a/c-merged fp32 pairs, sW[k*32+h] = (W1a[k][h], W1b[k][h]).
    // 16 KB. sX4 = 4 rows of X as float4 (1 KB). Phase B reuses sW as sC (2 KB).
    __shared__ __align__(16) float2 sW[FM * HID];     // [k][h], 16 KB
    __shared__ __align__(16) float4 sX4[4][16];
    __half2* sC = reinterpret_cast<__half2*>(sW);

    const int t    = threadIdx.x;
    const int warp = t >> 5;
    const int lane = t & 31;
    const int bid  = blockIdx.x + 8 * blockIdx.y + 256 * blockIdx.z;  // 0..1023

    // ============ Phase A: prep — 4 rows per block, 1 row per warp ======
    // Stage W1 merged. W1a = 2048 floats = 512 float4s -> 4 per thread.
    #pragma unroll
    for (int q = 0; q < 4; q++) {
        int idx4 = t + 128 * q;              // 0..511 : which float4 of W1a
        float4 wa = reinterpret_cast<const float4*>(W1)[idx4];         // W1a
        float4 wc = reinterpret_cast<const float4*>(W1)[512 + idx4];   // W1b
        float2* dst = &sW[idx4 * 4];
        reinterpret_cast<float4*>(dst)[0] = make_float4(wa.x, wc.x, wa.y, wc.y);
        reinterpret_cast<float4*>(dst)[1] = make_float4(wa.z, wc.z, wa.w, wc.w);
    }

    const int row = 4 * bid + warp;   // 0..4095; warp owns one row
    // Stage this warp's X row (64 floats = 16 float4): lane<16 loads one.
    if (lane < 16)
        sX4[warp][lane] = reinterpret_cast<const float4*>(X)[row * 16 + lane];
    const float bias = b1[lane];
    __syncthreads();

    {
        float a = bias;   // fold b1 into A'
        float c = 0.0f;
        #pragma unroll
        for (int k4 = 0; k4 < 16; k4++) {
            float4 xv = sX4[warp][k4];                 // LDS.128 broadcast
            float2 w0 = sW[(4 * k4 + 0) * 32 + lane];  // LDS.64 each
            float2 w1 = sW[(4 * k4 + 1) * 32 + lane];
            float2 w2v = sW[(4 * k4 + 2) * 32 + lane];
            float2 w3 = sW[(4 * k4 + 3) * 32 + lane];
            a = fmaf(xv.x, w0.x, a); c = fmaf(xv.x, w0.y, c);
            a = fmaf(xv.y, w1.x, a); c = fmaf(xv.y, w1.y, c);
            a = fmaf(xv.z, w2v.x, a); c = fmaf(xv.z, w2v.y, c);
            a = fmaf(xv.w, w3.x, a); c = fmaf(xv.w, w3.y, c);
        }
        reinterpret_cast<__half*>(g_A)[row * HID + lane] = __float2half_rn(a);
        reinterpret_cast<__half*>(g_C)[row * HID + lane] = __float2half_rn(c);
    }

    // All blocks: pack W2/2 + b2/2 (cheap; overlaps stragglers).
    __half2 w2h[16];
    #pragma unroll
    for (int k = 0; k < 16; k++)
        w2h[k] = __floats2half2_rn(0.5f * W2[2 * k], 0.5f * W2[2 * k + 1]);
    const float bias2 = 0.5f * b2[0];
    const __half2 binit = __halves2half2(__float2half_rn(bias2),
                                         __ushort_as_half((unsigned short)0));
    const __half2 hzero = __float2half2_rn(0.0f);

    // ============ Grid barrier (all 1024 blocks resident, 1 wave) =======
    __syncthreads();   // all prep STGs issued; all sW reads done
    if (t == 0) {
        unsigned my_gen = *(volatile unsigned*)&g_gen;  // read BEFORE arriving
        __threadfence();                                 // release g_A/g_C writes
        unsigned old = atomicAdd(&g_count, 1);
        if (old == NBLOCKS - 1) {
            g_count = 0;                                 // reset for next replay
            __threadfence();
            atomicAdd(&g_gen, 1);                        // release everyone
        } else {
            unsigned g;
            do {
                __nanosleep(32);
                asm volatile("ld.acquire.gpu.u32 %0, [%1];"
                             : "=r"(g) : "l"(&g_gen) : "memory");
            } while (g == my_gen);
        }
    }
    __syncthreads();

    // ============ Phase B: pairwise tanh + dot + sigmoid ================
    const int b  = blockIdx.z;
    const int j  = blockIdx.x * JT + t;
    const int i0 = blockIdx.y * I_CHUNK;

    // C tile (I_CHUNK rows x 16 half2 = 2 KB): 128 float4, one per thread.
    reinterpret_cast<float4*>(sC)[t] =
        __ldcg(reinterpret_cast<const float4*>(g_C + ((size_t)b * NN + i0) * 16) + t);

    // Per-thread A' row (register-resident).
    float4 av[4];
    const float4* gA = reinterpret_cast<const float4*>(g_A + ((size_t)b * NN + j) * 16);
    #pragma unroll
    for (int q = 0; q < 4; q++) av[q] = __ldcg(gA + q);
    const __half2* Aj = reinterpret_cast<const __half2*>(av);

    __syncthreads();

    float* outp = out + (size_t)b * NN * NN + (size_t)i0 * NN + j;

    #pragma unroll 4
    for (int ii = 0; ii < I_CHUNK; ii += 2) {
        const float4* crow0 = reinterpret_cast<const float4*>(sC + ii * 16);
        const float4* crow1 = reinterpret_cast<const float4*>(sC + (ii + 1) * 16);

        // Two independent accumulation chains (i and i+1).
        __half2 a0 = binit, a1 = hzero, a2 = hzero, a3 = hzero;   // i
        __half2 b0 = binit, b1v = hzero, b2v = hzero, b3 = hzero; // i+1

        #pragma unroll
        for (int q = 0; q < 4; q++) {
            float4 cv0 = crow0[q];                      // broadcast LDS.128
            float4 cv1 = crow1[q];
            const __half2* c0 = reinterpret_cast<const __half2*>(&cv0);
            const __half2* c1 = reinterpret_cast<const __half2*>(&cv1);

            __half2 t00 = tanh2_approx(__hadd2(Aj[4 * q + 0], c0[0]));
            __half2 t10 = tanh2_approx(__hadd2(Aj[4 * q + 0], c1[0]));
            __half2 t01 = tanh2_approx(__hadd2(Aj[4 * q + 1], c0[1]));
            __half2 t11 = tanh2_approx(__hadd2(Aj[4 * q + 1], c1[1]));
            __half2 t02 = tanh2_approx(__hadd2(Aj[4 * q + 2], c0[2]));
            __half2 t12 = tanh2_approx(__hadd2(Aj[4 * q + 2], c1[2]));
            __half2 t03 = tanh2_approx(__hadd2(Aj[4 * q + 3], c0[3]));
            __half2 t13 = tanh2_approx(__hadd2(Aj[4 * q + 3], c1[3]));

            a0  = __hfma2(t00, w2h[4 * q + 0], a0);
            b0  = __hfma2(t10, w2h[4 * q + 0], b0);
            a1  = __hfma2(t01, w2h[4 * q + 1], a1);
            b1v = __hfma2(t11, w2h[4 * q + 1], b1v);
            a2  = __hfma2(t02, w2h[4 * q + 2], a2);
            b2v = __hfma2(t12, w2h[4 * q + 2], b2v);
            a3  = __hfma2(t03, w2h[4 * q + 3], a3);
            b3  = __hfma2(t13, w2h[4 * q + 3], b3);
        }

        // Lean epilogue per i: 3 HADD2 + 1 HADD + 1 cvt + MUFU + FFMA + STG.
        __half2 sa = __hadd2(__hadd2(a0, a1), __hadd2(a2, a3));
        __half2 sb = __hadd2(__hadd2(b0, b1v), __hadd2(b2v, b3));
        float hla = __half2float(__hadd(__low2half(sa), __high2half(sa)));
        float hlb = __half2float(__hadd(__low2half(sb), __high2half(sb)));

        outp[(size_t)ii * NN]       = fmaf(0.5f, tanhf_approx(hla), 0.5f);
        outp[(size_t)(ii + 1) * NN] = fmaf(0.5f, tanhf_approx(hlb), 0.5f);
    }
}

// ---------------------------------------------------------------------------
// Launch: ONE graph-capturable kernel, no allocations, no syncs.
// Inputs (metadata order): X, W1, b1, W2, b2. Output: float32 [4,1024,1024].
// ---------------------------------------------------------------------------
extern "C" void kernel_launch(void* const* d_in, const int* in_sizes, int n_in,
                              void* d_out, int out_size)
{
    const float* X  = (const float*)d_in[0];
    const float* W1 = (const float*)d_in[1];
    const float* b1 = (const float*)d_in[2];
    const float* W2 = (const float*)d_in[3];
    const float* b2 = (const float*)d_in[4];
    float* out = (float*)d_out;

    dim3 grid(NN / JT, NN / I_CHUNK, BB);   // (8, 32, 4) = 1024 blocks, 1 wave
    fused_kernel<<<grid, JT>>>(X, W1, b1, W2, b2, out);
}

// round 16
// speedup vs baseline: 1.0942x; 1.0942x over previous
#include <cuda_runtime.h>
#include <cuda_fp16.h>

// Problem constants (fixed by the reference: B=4, N=1024, FMAP=64, HID=32)
#define BB 4
#define NN 1024
#define FM 64
#define HID 32
#define ROWS (BB * NN)        // 4096
#define I_CHUNK 32
#define JT 128

// Projections, packed as half (32 per row = 16 half2). Written by prep.
__device__ __align__(16) __half2 g_A[ROWS * 16];  // A' = X@W1a + b1
__device__ __align__(16) __half2 g_C[ROWS * 16];  // C  = X@W1b

__device__ __forceinline__ __half2 tanh2_approx(__half2 x) {
    unsigned xi = *reinterpret_cast<unsigned*>(&x);
    unsigned ri;
    asm("tanh.approx.f16x2 %0, %1;" : "=r"(ri) : "r"(xi));
    return *reinterpret_cast<__half2*>(&ri);
}

__device__ __forceinline__ float tanhf_approx(float x) {
    float r;
    asm("tanh.approx.f32 %0, %1;" : "=f"(r) : "f"(x));
    return r;
}

// ---------------------------------------------------------------------------
// prep: 512 blocks x 256 threads, 1 row per warp. W1 half2-packed in smem
// (k-pairs), X as float2 broadcasts — the fastest measured prep form (R13).
// ---------------------------------------------------------------------------
__global__ __launch_bounds__(256) void prep_kernel(
    const float* __restrict__ X,    // [ROWS, 64]
    const float* __restrict__ W1,   // [128, 32]
    const float* __restrict__ b1)   // [32]
{
    __shared__ __align__(16) __half2 sWa[32 * 32];   // [kp][h], a-half, 4 KB
    __shared__ __align__(16) __half2 sWc[32 * 32];   // [kp][h], c-half, 4 KB
    __shared__ __align__(16) float2  sX2[8][32];

    const int t    = threadIdx.x;
    const int warp = t >> 5;
    const int lane = t & 31;

    // Stage W1 packed: entry (kp,h) = half2(W1[2kp][h], W1[2kp+1][h]).
    #pragma unroll
    for (int q = 0; q < 4; q++) {
        int idx = t + 256 * q;          // 0..1023
        int kp = idx >> 5, h = idx & 31;
        sWa[idx] = __floats2half2_rn(W1[kp * 64 + h],        W1[kp * 64 + 32 + h]);
        sWc[idx] = __floats2half2_rn(W1[2048 + kp * 64 + h], W1[2048 + kp * 64 + 32 + h]);
    }

    const int row = blockIdx.x * 8 + warp;   // 0..4095
    sX2[warp][lane] = reinterpret_cast<const float2*>(X)[row * 32 + lane];
    const float bias = b1[lane];
    __syncthreads();

    float a = bias;   // fold b1 into A'
    float c = 0.0f;
    #pragma unroll
    for (int kp = 0; kp < 32; kp++) {
        float2 xk = sX2[warp][kp];                       // LDS.64 broadcast
        float2 fa = __half22float2(sWa[kp * 32 + lane]); // LDS.32 each
        float2 fc = __half22float2(sWc[kp * 32 + lane]);
        a = fmaf(xk.x, fa.x, a); a = fmaf(xk.y, fa.y, a);
        c = fmaf(xk.x, fc.x, c); c = fmaf(xk.y, fc.y, c);
    }
    reinterpret_cast<__half*>(g_A)[row * HID + lane] = __float2half_rn(a);
    reinterpret_cast<__half*>(g_C)[row * HID + lane] = __float2half_rn(c);

    // Let the dependent pair_kernel launch as soon as all CTAs got here.
    cudaTriggerProgrammaticLaunchCompletion();
}

// ---------------------------------------------------------------------------
// pair: grid (8, 32, 4) = 1024 blocks x 128 threads. PDL: prologue overlaps
// prep; cudaGridDependencySynchronize() gates the g_A/g_C reads.
// ---------------------------------------------------------------------------
__global__ __launch_bounds__(JT, 8) void pair_kernel(
    const float* __restrict__ W2,   // [32]
    const float* __restrict__ b2,   // [1]
    float* __restrict__ out)        // [B, N, N]
{
    __shared__ __align__(16) __half2 sC[I_CHUNK * 16];   // 2 KB

    const int b  = blockIdx.z;
    const int j  = blockIdx.x * JT + threadIdx.x;
    const int i0 = blockIdx.y * I_CHUNK;
    const int t  = threadIdx.x;

    // ---- Prologue (overlaps prep under PDL): W2/2 pack + b2/2 ----
    __half2 w2h[16];
    #pragma unroll
    for (int k = 0; k < 16; k++)
        w2h[k] = __floats2half2_rn(0.5f * W2[2 * k], 0.5f * W2[2 * k + 1]);
    const float bias2 = 0.5f * b2[0];
    const __half2 binit = __halves2half2(__float2half_rn(bias2),
                                         __ushort_as_half((unsigned short)0));
    const __half2 hzero = __float2half2_rn(0.0f);
    float* outp = out + (size_t)b * NN * NN + (size_t)i0 * NN + j;

    // ---- Wait for prep's writes to be visible ----
    cudaGridDependencySynchronize();

    // C tile (I_CHUNK rows x 16 half2 = 2 KB): 128 float4, one per thread.
    reinterpret_cast<float4*>(sC)[t] =
        __ldcg(reinterpret_cast<const float4*>(g_C + ((size_t)b * NN + i0) * 16) + t);

    // Per-thread A' row (register-resident).
    float4 av[4];
    const float4* gA = reinterpret_cast<const float4*>(g_A + ((size_t)b * NN + j) * 16);
    #pragma unroll
    for (int q = 0; q < 4; q++) av[q] = __ldcg(gA + q);
    const __half2* Aj = reinterpret_cast<const __half2*>(av);

    __syncthreads();

    #pragma unroll 4
    for (int ii = 0; ii < I_CHUNK; ii += 2) {
        const float4* crow0 = reinterpret_cast<const float4*>(sC + ii * 16);
        const float4* crow1 = reinterpret_cast<const float4*>(sC + (ii + 1) * 16);

        // Two independent accumulation chains (i and i+1).
        __half2 a0 = binit, a1 = hzero, a2 = hzero, a3 = hzero;   // i
        __half2 b0 = binit, b1v = hzero, b2v = hzero, b3 = hzero; // i+1

        #pragma unroll
        for (int q = 0; q < 4; q++) {
            float4 cv0 = crow0[q];                      // broadcast LDS.128
            float4 cv1 = crow1[q];
            const __half2* c0 = reinterpret_cast<const __half2*>(&cv0);
            const __half2* c1 = reinterpret_cast<const __half2*>(&cv1);

            __half2 t00 = tanh2_approx(__hadd2(Aj[4 * q + 0], c0[0]));
            __half2 t10 = tanh2_approx(__hadd2(Aj[4 * q + 0], c1[0]));
            __half2 t01 = tanh2_approx(__hadd2(Aj[4 * q + 1], c0[1]));
            __half2 t11 = tanh2_approx(__hadd2(Aj[4 * q + 1], c1[1]));
            __half2 t02 = tanh2_approx(__hadd2(Aj[4 * q + 2], c0[2]));
            __half2 t12 = tanh2_approx(__hadd2(Aj[4 * q + 2], c1[2]));
            __half2 t03 = tanh2_approx(__hadd2(Aj[4 * q + 3], c0[3]));
            __half2 t13 = tanh2_approx(__hadd2(Aj[4 * q + 3], c1[3]));

            a0  = __hfma2(t00, w2h[4 * q + 0], a0);
            b0  = __hfma2(t10, w2h[4 * q + 0], b0);
            a1  = __hfma2(t01, w2h[4 * q + 1], a1);
            b1v = __hfma2(t11, w2h[4 * q + 1], b1v);
            a2  = __hfma2(t02, w2h[4 * q + 2], a2);
            b2v = __hfma2(t12, w2h[4 * q + 2], b2v);
            a3  = __hfma2(t03, w2h[4 * q + 3], a3);
            b3  = __hfma2(t13, w2h[4 * q + 3], b3);
        }

        // Lean epilogue per i: 3 HADD2 + 1 HADD + 1 cvt + MUFU + FFMA + STG.
        __half2 sa = __hadd2(__hadd2(a0, a1), __hadd2(a2, a3));
        __half2 sb = __hadd2(__hadd2(b0, b1v), __hadd2(b2v, b3));
        float hla = __half2float(__hadd(__low2half(sa), __high2half(sa)));
        float hlb = __half2float(__hadd(__low2half(sb), __high2half(sb)));

        outp[(size_t)ii * NN]       = fmaf(0.5f, tanhf_approx(hla), 0.5f);
        outp[(size_t)(ii + 1) * NN] = fmaf(0.5f, tanhf_approx(hlb), 0.5f);
    }
}

// ---------------------------------------------------------------------------
// Launch: prep, then pair with Programmatic Dependent Launch so pair's
// prologue overlaps prep. Fallback to a plain launch if PDL is rejected.
// Graph-capturable: kernel launches only, no allocs, no syncs.
// ---------------------------------------------------------------------------
extern "C" void kernel_launch(void* const* d_in, const int* in_sizes, int n_in,
                              void* d_out, int out_size)
{
    const float* X  = (const float*)d_in[0];
    const float* W1 = (const float*)d_in[1];
    const float* b1 = (const float*)d_in[2];
    const float* W2 = (const float*)d_in[3];
    const float* b2 = (const float*)d_in[4];
    float* out = (float*)d_out;

    prep_kernel<<<ROWS / 8, 256>>>(X, W1, b1);

    dim3 grid(NN / JT, NN / I_CHUNK, BB);   // (8, 32, 4) = 1024 blocks

    cudaLaunchConfig_t cfg = {};
    cfg.gridDim = grid;
    cfg.blockDim = dim3(JT, 1, 1);
    cfg.dynamicSmemBytes = 0;
    cfg.stream = 0;
    cudaLaunchAttribute attr[1];
    attr[0].id = cudaLaunchAttributeProgrammaticStreamSerialization;
    attr[0].val.programmaticStreamSerializationAllowed = 1;
    cfg.attrs = attr;
    cfg.numAttrs = 1;

    cudaError_t e = cudaLaunchKernelEx(&cfg, pair_kernel, W2, b2, out);
    if (e != cudaSuccess) {
        (void)cudaGetLastError();               // clear sticky error
        pair_kernel<<<grid, JT>>>(W2, b2, out); // plain fallback (serialized)
    }
}